// round 5
// baseline (speedup 1.0000x reference)
#include <cuda_runtime.h>

// Blur_80281528697499: depthwise UpFirDn2D(up=2, dn=2, 4x4) == 2x2 stencil
// with odd-odd filter taps. x:(8,256,128,128) f32 -> out same shape.
//
// Row-strip blocking, R=8: one warp = 8 output rows x 128 px (32 lanes x
// float4). Front-loads 9 input rows as 9 independent LDG.128 (144 B in
// flight per thread) -> deep MLP feeds HBM. Reads per output = 1.125.
// Neighbor (x+4) element comes from an on-demand __shfl_down in the compute
// loop (keeps register count down; shuffle pipe is idle anyway).
// Block = 8 warps = 64 rows; plane (128 rows) = 2 blocks; grid = 2048*2.

#define NB 8
#define NC 256
#define NH 128
#define NW 128
#define R  8   // output rows per warp

__global__ void __launch_bounds__(256) blur2x2_strip8_kernel(
    const float* __restrict__ x,
    const float* __restrict__ filt,
    float* __restrict__ out)
{
    const int pblk  = blockIdx.x & 1;          // 2 blocks per plane
    const int plane = blockIdx.x >> 1;         // b*C + c, 0..2047
    const int c     = plane & (NC - 1);

    const int warp  = threadIdx.x >> 5;
    const int lane  = threadIdx.x & 31;
    const int y0    = pblk * 64 + warp * R;    // first output row of strip

    const float4* base = reinterpret_cast<const float4*>(
        x + (size_t)plane * (NH * NW));

    // Front-load R+1 = 9 rows (all independent -> 9 LDG.128 in flight).
    float4 r[R + 1];
    const bool last_strip = (y0 + R >= NH);    // warp-uniform
    #pragma unroll
    for (int i = 0; i < R; i++)
        r[i] = base[(y0 + i) * (NW / 4) + lane];
    if (!last_strip)
        r[R] = base[(y0 + R) * (NW / 4) + lane];
    else
        r[R] = make_float4(0.0f, 0.0f, 0.0f, 0.0f);

    // Per-channel filter taps (only odd-odd taps of the 4x4 contribute).
    // Loaded after the bulk LDGs are issued so they don't steal queue slots.
    const float* fp = filt + c * 16;
    const float wA = __ldg(fp + 5);    // f[1][1]
    const float wB = __ldg(fp + 7);    // f[1][3]
    const float wC = __ldg(fp + 13);   // f[3][1]
    const float wD = __ldg(fp + 15);   // f[3][3]

    float4* obase = reinterpret_cast<float4*>(out) +
                    (size_t)plane * (NH * NW / 4) + lane;

    // Neighbor of row 0 computed up front; each iteration computes the next
    // row's neighbor on demand (shuffles overlap with store issue).
    float an = __shfl_down_sync(0xffffffffu, r[0].x, 1);
    if (lane == 31) an = 0.0f;

    #pragma unroll
    for (int i = 0; i < R; i++) {
        float bn = __shfl_down_sync(0xffffffffu, r[i + 1].x, 1);
        if (lane == 31) bn = 0.0f;

        const float4 a = r[i];
        const float4 b = r[i + 1];
        float4 o;
        o.x = wA * a.x + wB * a.y + wC * b.x + wD * b.y;
        o.y = wA * a.y + wB * a.z + wC * b.y + wD * b.z;
        o.z = wA * a.z + wB * a.w + wC * b.z + wD * b.w;
        o.w = wA * a.w + wB * an  + wC * b.w + wD * bn;
        obase[(y0 + i) * (NW / 4)] = o;

        an = bn;
    }
}

extern "C" void kernel_launch(void* const* d_in, const int* in_sizes, int n_in,
                              void* d_out, int out_size)
{
    const float* x    = (const float*)d_in[0];   // (8,256,128,128) f32
    const float* filt = (const float*)d_in[1];   // (256,1,4,4) f32
    float* out = (float*)d_out;                  // (8,256,128,128) f32

    const int planes = NB * NC;                  // 2048
    const int blocks = planes * 2;               // 4096
    blur2x2_strip8_kernel<<<blocks, 256>>>(x, filt, out);
}

// round 6
// speedup vs baseline: 1.0135x; 1.0135x over previous
#include <cuda_runtime.h>

// Blur_80281528697499: depthwise UpFirDn2D(up=2, dn=2, 4x4) == 2x2 stencil
// with odd-odd filter taps. x:(8,256,128,128) f32 -> out same shape.
//
// R=4 row-strip (best measured config) + streaming stores.
// One warp = 4 output rows x 128 px (32 lanes x float4); front-loads 5
// independent LDG.128 (MLP=5). Outputs stored with __stcs (evict-first:
// never re-read, keeps L2 for the strip-boundary input rows).
// __launch_bounds__(256, 4) grants a 64-reg budget so ptxas keeps the full
// 5-row load batch live (R8 experiment showed a 32-reg budget silently
// re-serializes the batch).

#define NB 8
#define NC 256
#define NH 128
#define NW 128
#define R  4   // output rows per warp

__global__ void __launch_bounds__(256, 4) blur2x2_strip_kernel(
    const float* __restrict__ x,
    const float* __restrict__ filt,
    float* __restrict__ out)
{
    const int pblk  = blockIdx.x & 3;          // 4 blocks per plane
    const int plane = blockIdx.x >> 2;         // b*C + c, 0..2047
    const int c     = plane & (NC - 1);

    const int warp  = threadIdx.x >> 5;
    const int lane  = threadIdx.x & 31;
    const int y0    = pblk * 32 + warp * R;    // first output row of strip

    const float4* base = reinterpret_cast<const float4*>(
        x + (size_t)plane * (NH * NW));

    // Front-load R+1 = 5 rows (independent -> 5 LDG.128 in flight).
    float4 r[R + 1];
    const bool last_strip = (y0 + R >= NH);    // warp-uniform
    #pragma unroll
    for (int i = 0; i < R; i++)
        r[i] = base[(y0 + i) * (NW / 4) + lane];
    if (!last_strip)
        r[R] = base[(y0 + R) * (NW / 4) + lane];
    else
        r[R] = make_float4(0.0f, 0.0f, 0.0f, 0.0f);

    // Per-channel filter taps (only odd-odd taps of the 4x4 contribute).
    const float* fp = filt + c * 16;
    const float wA = __ldg(fp + 5);    // f[1][1]
    const float wB = __ldg(fp + 7);    // f[1][3]
    const float wC = __ldg(fp + 13);   // f[3][1]
    const float wD = __ldg(fp + 15);   // f[3][3]

    // Next-lane .x for each row (right neighbor of the .w element).
    float n[R + 1];
    #pragma unroll
    for (int i = 0; i < R + 1; i++) {
        n[i] = __shfl_down_sync(0xffffffffu, r[i].x, 1);
        if (lane == 31) n[i] = 0.0f;           // right boundary -> 0
    }

    float4* obase = reinterpret_cast<float4*>(out) +
                    (size_t)plane * (NH * NW / 4) + lane;

    #pragma unroll
    for (int i = 0; i < R; i++) {
        const float4 a = r[i];
        const float4 b = r[i + 1];
        const float  an = n[i];
        const float  bn = n[i + 1];
        float4 o;
        o.x = wA * a.x + wB * a.y + wC * b.x + wD * b.y;
        o.y = wA * a.y + wB * a.z + wC * b.y + wD * b.z;
        o.z = wA * a.z + wB * a.w + wC * b.z + wD * b.w;
        o.w = wA * a.w + wB * an  + wC * b.w + wD * bn;
        __stcs(obase + (y0 + i) * (NW / 4), o);   // streaming store
    }
}

extern "C" void kernel_launch(void* const* d_in, const int* in_sizes, int n_in,
                              void* d_out, int out_size)
{
    const float* x    = (const float*)d_in[0];   // (8,256,128,128) f32
    const float* filt = (const float*)d_in[1];   // (256,1,4,4) f32
    float* out = (float*)d_out;                  // (8,256,128,128) f32

    const int planes = NB * NC;                  // 2048
    const int blocks = planes * 4;               // 8192
    blur2x2_strip_kernel<<<blocks, 256>>>(x, filt, out);
}